// round 14
// baseline (speedup 1.0000x reference)
#include <cuda_runtime.h>
#include <cstdint>

#define B_   2
#define N_   131072
#define K_   9
#define P_   4
#define D_   4
#define CI_  8
#define CO_  8
#define NTOT (B_ * N_)   // 262144
#define MOUT (P_ * D_ * CO_)   // 128 floats per m

typedef unsigned long long u64;

// ---- packed f32x2 helpers ----
__device__ __forceinline__ u64 pk2(float lo, float hi) {
    u64 r; asm("mov.b64 %0, {%1, %2};" : "=l"(r) : "f"(lo), "f"(hi)); return r;
}
__device__ __forceinline__ void upk2(float &lo, float &hi, u64 v) {
    asm("mov.b64 {%0, %1}, %2;" : "=f"(lo), "=f"(hi) : "l"(v));
}
__device__ __forceinline__ u64 fma2(u64 a, u64 b, u64 c) {
    u64 d; asm("fma.rn.f32x2 %0, %1, %2, %3;" : "=l"(d) : "l"(a), "l"(b), "l"(c)); return d;
}
__device__ __forceinline__ u64 add2(u64 a, u64 b) {
    u64 d; asm("add.rn.f32x2 %0, %1, %2;" : "=l"(d) : "l"(a), "l"(b)); return d;
}

// A (pre-scaled by C_d) in shared as 16B chunks: A16[d][j][h][p][ch]; for
// fixed (d,j,h) the 8 (p,ch) lanes hit 8 consecutive 16B chunks = one 128B
// span -> conflict-free broadcast LDS.128.   (c = ch*4 + j)
__device__ __forceinline__ int a16_idx(int d, int j, int h, int p, int ch) {
    return ((((d * 4 + j) * 2 + h) * P_ + p) * 2 + ch);
}

// rotated 32B chunk store: writes v[0..3] (= one kept-d row) at o + off,
// h-order rotated by sel so the two STS of the pair hit different granules.
__device__ __forceinline__ void store_row(float* o, int off, int sel,
                                          u64 v0, u64 v1, u64 v2, u64 v3) {
    ulonglong2 vlo, vhi;
    vlo.x = v0; vlo.y = v1;
    vhi.x = v2; vhi.y = v3;
    *(ulonglong2*)(o + off + sel * 4)       = sel ? vhi : vlo;
    *(ulonglong2*)(o + off + (sel ^ 1) * 4) = sel ? vlo : vhi;
}

__global__ __launch_bounds__(128, 5)
void pol_kernel(const float* __restrict__ x,
                const float* __restrict__ dx,
                const float* __restrict__ dy,
                const int*   __restrict__ adj,
                const float* __restrict__ phis,
                const float* __restrict__ dists,
                const float* __restrict__ sigma,
                const float* __restrict__ A,
                float* __restrict__ out)
{
    __shared__ __align__(16)  ulonglong2 A16[256];        // 4 KB
    __shared__ __align__(16)  float2 dxy_s[K_][32];       // [k][block-local m]
    __shared__ __align__(8)   int    adj_s[K_][32];
    __shared__ __align__(128) float  outbuf[32 * MOUT];   // 16 KB, exact global layout
    __shared__ float s_cos[P_], s_sin[P_], s_q[D_], s_nh;

    const int tid    = threadIdx.x;
    const int base_m = blockIdx.x * 32;            // block covers 32 m
    const int nb     = base_m & (N_ - 1);

    // ---- stage A (pre-scaled by C_d): one (d,c,p) entry per thread ----
    {
        int p = tid & 3, c = (tid >> 2) & 7, d = tid >> 5;
        int j = c & 3, ch = c >> 2;
        float sg   = fmaxf(sigma[0], 1e-10f);
        float is2  = 1.0f / (sg * sg);
        float nhl  = -0.5f * is2;
        float norm = rsqrtf(6.283185307179586f * sg * sg);
        float td   = dists[d];
        float Cd   = expf(nhl * td * td) * norm;
        int g = p * (D_ * CI_ * CO_) + d * (CI_ * CO_) + c * CO_;
        ulonglong2 h0, h1;
        h0.x = pk2(A[g + 0] * Cd, A[g + 1] * Cd);
        h0.y = pk2(A[g + 2] * Cd, A[g + 3] * Cd);
        h1.x = pk2(A[g + 4] * Cd, A[g + 5] * Cd);
        h1.y = pk2(A[g + 6] * Cd, A[g + 7] * Cd);
        A16[a16_idx(d, j, 0, p, ch)] = h0;
        A16[a16_idx(d, j, 1, p, ch)] = h1;
    }
    // ---- stage dx/dy/adj transposed (known-good R4 path) ----
    if (tid < 72) {
        float4 xv = __ldg((const float4*)(dx + (size_t)base_m * K_) + tid);
        float4 yv = __ldg((const float4*)(dy + (size_t)base_m * K_) + tid);
        int4   av = __ldg((const int4*)  (adj + (size_t)nb * K_) + tid);
        int e = tid * 4;
        int ml, k;
        ml = (e+0)/9; k = (e+0)%9; dxy_s[k][ml].x = xv.x; dxy_s[k][ml].y = yv.x; adj_s[k][ml] = av.x;
        ml = (e+1)/9; k = (e+1)%9; dxy_s[k][ml].x = xv.y; dxy_s[k][ml].y = yv.y; adj_s[k][ml] = av.y;
        ml = (e+2)/9; k = (e+2)%9; dxy_s[k][ml].x = xv.z; dxy_s[k][ml].y = yv.z; adj_s[k][ml] = av.z;
        ml = (e+3)/9; k = (e+3)%9; dxy_s[k][ml].x = xv.w; dxy_s[k][ml].y = yv.w; adj_s[k][ml] = av.w;
    }
    if (tid == 0) {
        float sg  = fmaxf(sigma[0], 1e-10f);
        float is2 = 1.0f / (sg * sg);
        s_nh = -0.5f * is2;
        #pragma unroll
        for (int p = 0; p < P_; p++) { s_cos[p] = cosf(phis[p]); s_sin[p] = sinf(phis[p]); }
        #pragma unroll
        for (int d = 0; d < D_; d++) s_q[d] = dists[d] * is2;
    }
    __syncthreads();

    const int wid  = tid >> 5;
    const int lane = tid & 31;
    const int m4   = lane >> 3;
    const int p    = (lane >> 1) & 3;
    const int ch   = lane & 1;

    const int mlA  = wid * 8 + m4 * 2;        // block-local m of this thread's pair
    const int b    = base_m >> 17;            // uniform per block (N_ = 2^17)

    const float cosp = s_cos[p], sinp = s_sin[p], nh = s_nh;
    const float q0 = s_q[0], q1 = s_q[1], q2 = s_q[2], q3 = s_q[3];

    const float* xb = x + (size_t)b * N_ * CI_ + ch * 4;

    u64 tA[D_][2], tB[D_][2];
    #pragma unroll
    for (int d = 0; d < D_; d++) {
        tA[d][0] = 0ull; tA[d][1] = 0ull;
        tB[d][0] = 0ull; tB[d][1] = 0ull;
    }

    #pragma unroll 3
    for (int k = 0; k < K_; k++) {
        float4 dd = *(const float4*)&dxy_s[k][mlA];      // dxA,dyA,dxB,dyB
        int2   aa = *(const int2*)&adj_s[k][mlA];
        float4 xa  = __ldg((const float4*)(xb + (size_t)aa.x * CI_));
        float4 xvb = __ldg((const float4*)(xb + (size_t)aa.y * CI_));

        float ra = nh * fmaf(dd.y, dd.y, dd.x * dd.x);
        float ca = fmaf(dd.y, sinp, dd.x * cosp);
        float rb = nh * fmaf(dd.w, dd.w, dd.z * dd.z);
        float cb = fmaf(dd.w, sinp, dd.z * cosp);

        float eA0 = __expf(fmaf(ca, q0, ra));
        float eA1 = __expf(fmaf(ca, q1, ra));
        float eA2 = __expf(fmaf(ca, q2, ra));
        float eA3 = __expf(fmaf(ca, q3, ra));
        float eB0 = __expf(fmaf(cb, q0, rb));
        float eB1 = __expf(fmaf(cb, q1, rb));
        float eB2 = __expf(fmaf(cb, q2, rb));
        float eB3 = __expf(fmaf(cb, q3, rb));

        u64 xa0 = pk2(xa.x, xa.y),   xa1 = pk2(xa.z, xa.w);
        u64 xb0 = pk2(xvb.x, xvb.y), xb1 = pk2(xvb.z, xvb.w);

        u64 w;
        w = pk2(eA0, eA0); tA[0][0] = fma2(w, xa0, tA[0][0]); tA[0][1] = fma2(w, xa1, tA[0][1]);
        w = pk2(eA1, eA1); tA[1][0] = fma2(w, xa0, tA[1][0]); tA[1][1] = fma2(w, xa1, tA[1][1]);
        w = pk2(eA2, eA2); tA[2][0] = fma2(w, xa0, tA[2][0]); tA[2][1] = fma2(w, xa1, tA[2][1]);
        w = pk2(eA3, eA3); tA[3][0] = fma2(w, xa0, tA[3][0]); tA[3][1] = fma2(w, xa1, tA[3][1]);
        w = pk2(eB0, eB0); tB[0][0] = fma2(w, xb0, tB[0][0]); tB[0][1] = fma2(w, xb1, tB[0][1]);
        w = pk2(eB1, eB1); tB[1][0] = fma2(w, xb0, tB[1][0]); tB[1][1] = fma2(w, xb1, tB[1][1]);
        w = pk2(eB2, eB2); tB[2][0] = fma2(w, xb0, tB[2][0]); tB[2][1] = fma2(w, xb1, tB[2][1]);
        w = pk2(eB3, eB3); tB[3][0] = fma2(w, xb0, tB[3][0]); tB[3][1] = fma2(w, xb1, tB[3][1]);
    }

    // ---- contraction (exchange-acc AFTER the FMAs); fins kept for both dk ----
    float* oA = outbuf + mlA * MOUT + p * (D_ * CO_);
    float* oB = oA + MOUT;
    const int sel = p & 1;     // h rotation (p parity)
    const int dkf = m4 & 1;    // dk rotation (m4 parity)

    u64 finA0[4], finA1[4], finB0[4], finB1[4];

    #pragma unroll
    for (int dk = 0; dk < 2; dk++) {
        const int d0 = dk, d1 = dk + 2;

        float tA0[4], tA1[4], tB0[4], tB1[4];
        upk2(tA0[0], tA0[1], tA[d0][0]);
        upk2(tA0[2], tA0[3], tA[d0][1]);
        upk2(tA1[0], tA1[1], tA[d1][0]);
        upk2(tA1[2], tA1[3], tA[d1][1]);
        upk2(tB0[0], tB0[1], tB[d0][0]);
        upk2(tB0[2], tB0[3], tB[d0][1]);
        upk2(tB1[0], tB1[1], tB[d1][0]);
        upk2(tB1[2], tB1[3], tB[d1][1]);

        u64 aA0[4] = {0,0,0,0}, aA1[4] = {0,0,0,0};
        u64 aB0[4] = {0,0,0,0}, aB1[4] = {0,0,0,0};
        #pragma unroll
        for (int j = 0; j < 4; j++) {
            ulonglong2 e0 = A16[a16_idx(d0, j, 0, p, ch)];
            ulonglong2 e1 = A16[a16_idx(d0, j, 1, p, ch)];
            u64 t_;
            t_ = pk2(tA0[j], tA0[j]);
            aA0[0] = fma2(t_, e0.x, aA0[0]); aA0[1] = fma2(t_, e0.y, aA0[1]);
            aA0[2] = fma2(t_, e1.x, aA0[2]); aA0[3] = fma2(t_, e1.y, aA0[3]);
            t_ = pk2(tB0[j], tB0[j]);
            aB0[0] = fma2(t_, e0.x, aB0[0]); aB0[1] = fma2(t_, e0.y, aB0[1]);
            aB0[2] = fma2(t_, e1.x, aB0[2]); aB0[3] = fma2(t_, e1.y, aB0[3]);

            ulonglong2 f0 = A16[a16_idx(d1, j, 0, p, ch)];
            ulonglong2 f1 = A16[a16_idx(d1, j, 1, p, ch)];
            t_ = pk2(tA1[j], tA1[j]);
            aA1[0] = fma2(t_, f0.x, aA1[0]); aA1[1] = fma2(t_, f0.y, aA1[1]);
            aA1[2] = fma2(t_, f1.x, aA1[2]); aA1[3] = fma2(t_, f1.y, aA1[3]);
            t_ = pk2(tB1[j], tB1[j]);
            aB1[0] = fma2(t_, f0.x, aB1[0]); aB1[1] = fma2(t_, f0.y, aB1[1]);
            aB1[2] = fma2(t_, f1.x, aB1[2]); aB1[3] = fma2(t_, f1.y, aB1[3]);
        }

        // exchange with partner lane (other c-half). Kept d = dk + 2*ch.
        #pragma unroll
        for (int o2 = 0; o2 < 4; o2++) {
            u64 sA = ch ? aA0[o2] : aA1[o2];
            u64 rA = __shfl_xor_sync(0xffffffffu, sA, 1);
            u64 kA = ch ? aA1[o2] : aA0[o2];
            u64 sB = ch ? aB0[o2] : aB1[o2];
            u64 rB = __shfl_xor_sync(0xffffffffu, sB, 1);
            u64 kB = ch ? aB1[o2] : aB0[o2];
            if (dk == 0) { finA0[o2] = add2(kA, rA); finB0[o2] = add2(kB, rB); }
            else         { finA1[o2] = add2(kA, rA); finB1[o2] = add2(kB, rB); }
        }
    }

    // ---- dual-rotated staging STS: dk order by m4 parity, h order by p parity.
    // Per inst the bank granule = 4ch + 2(dk^m4&1) + (h^p&1) -> 8 groups x 4 lanes
    // = 4-way = the 512B/inst floor.
    {
        const int off1 = (2 * ch + dkf) * CO_;        // first-stored d row
        const int off2 = (2 * ch + (dkf ^ 1)) * CO_;  // second
        u64 vA0 = dkf ? finA1[0] : finA0[0];
        u64 vA1 = dkf ? finA1[1] : finA0[1];
        u64 vA2 = dkf ? finA1[2] : finA0[2];
        u64 vA3 = dkf ? finA1[3] : finA0[3];
        u64 wA0 = dkf ? finA0[0] : finA1[0];
        u64 wA1 = dkf ? finA0[1] : finA1[1];
        u64 wA2 = dkf ? finA0[2] : finA1[2];
        u64 wA3 = dkf ? finA0[3] : finA1[3];
        u64 vB0 = dkf ? finB1[0] : finB0[0];
        u64 vB1 = dkf ? finB1[1] : finB0[1];
        u64 vB2 = dkf ? finB1[2] : finB0[2];
        u64 vB3 = dkf ? finB1[3] : finB0[3];
        u64 wB0 = dkf ? finB0[0] : finB1[0];
        u64 wB1 = dkf ? finB0[1] : finB1[1];
        u64 wB2 = dkf ? finB0[2] : finB1[2];
        u64 wB3 = dkf ? finB0[3] : finB1[3];

        store_row(oA, off1, sel, vA0, vA1, vA2, vA3);
        store_row(oB, off1, sel, vB0, vB1, vB2, vB3);
        store_row(oA, off2, sel, wA0, wA1, wA2, wA3);
        store_row(oB, off2, sel, wB0, wB1, wB2, wB3);
    }
    __syncthreads();

    // ---- single TMA bulk store: smem -> global, off the LSU/L1 path ----
    if (tid == 0) {
        asm volatile("fence.proxy.async.shared::cta;" ::: "memory");
        uint32_t saddr = (uint32_t)__cvta_generic_to_shared(outbuf);
        float* gdst = out + (size_t)base_m * MOUT;
        asm volatile(
            "cp.async.bulk.global.shared::cta.bulk_group [%0], [%1], %2;"
            :: "l"(gdst), "r"(saddr), "r"(32 * MOUT * 4) : "memory");
        asm volatile("cp.async.bulk.commit_group;" ::: "memory");
        asm volatile("cp.async.bulk.wait_group.read 0;" ::: "memory");
    }
}

extern "C" void kernel_launch(void* const* d_in, const int* in_sizes, int n_in,
                              void* d_out, int out_size)
{
    const float* x     = (const float*)d_in[0];
    const float* dx    = (const float*)d_in[1];
    const float* dy    = (const float*)d_in[2];
    const int*   adj   = (const int*)d_in[3];
    const float* phis  = (const float*)d_in[4];
    const float* dists = (const float*)d_in[5];
    const float* sigma = (const float*)d_in[6];
    const float* A     = (const float*)d_in[7];
    float* out = (float*)d_out;

    dim3 grid(NTOT / 32);   // 8192 blocks, 128 threads, each thread 2 m
    pol_kernel<<<grid, 128>>>(x, dx, dy, adj, phis, dists, sigma, A, out);
    (void)in_sizes; (void)n_in; (void)out_size;
}

// round 15
// speedup vs baseline: 1.0094x; 1.0094x over previous
#include <cuda_runtime.h>
#include <cstdint>

#define B_   2
#define N_   131072
#define K_   9
#define P_   4
#define D_   4
#define CI_  8
#define CO_  8
#define NTOT (B_ * N_)   // 262144
#define MOUT (P_ * D_ * CO_)   // 128 floats per m
#define MPAD 132               // padded smem per-m stride (33 granules, odd mod 8)

typedef unsigned long long u64;

// ---- packed f32x2 helpers ----
__device__ __forceinline__ u64 pk2(float lo, float hi) {
    u64 r; asm("mov.b64 %0, {%1, %2};" : "=l"(r) : "f"(lo), "f"(hi)); return r;
}
__device__ __forceinline__ void upk2(float &lo, float &hi, u64 v) {
    asm("mov.b64 {%0, %1}, %2;" : "=f"(lo), "=f"(hi) : "l"(v));
}
__device__ __forceinline__ u64 fma2(u64 a, u64 b, u64 c) {
    u64 d; asm("fma.rn.f32x2 %0, %1, %2, %3;" : "=l"(d) : "l"(a), "l"(b), "l"(c)); return d;
}
__device__ __forceinline__ u64 add2(u64 a, u64 b) {
    u64 d; asm("add.rn.f32x2 %0, %1, %2;" : "=l"(d) : "l"(a), "l"(b)); return d;
}

// A (pre-scaled by C_d) in shared as 16B chunks: A16[d][j][h][p][ch]; for
// fixed (d,j,h) the 8 (p,ch) lanes hit 8 consecutive 16B chunks = one 128B
// span -> conflict-free broadcast LDS.128.   (c = ch*4 + j)
__device__ __forceinline__ int a16_idx(int d, int j, int h, int p, int ch) {
    return ((((d * 4 + j) * 2 + h) * P_ + p) * 2 + ch);
}

__global__ __launch_bounds__(128, 5)
void pol_kernel(const float* __restrict__ x,
                const float* __restrict__ dx,
                const float* __restrict__ dy,
                const int*   __restrict__ adj,
                const float* __restrict__ phis,
                const float* __restrict__ dists,
                const float* __restrict__ sigma,
                const float* __restrict__ A,
                float* __restrict__ out)
{
    __shared__ __align__(16)  ulonglong2 A16[256];        // 4 KB
    __shared__ __align__(16)  float2 dxy_s[K_][32];       // [k][block-local m]
    __shared__ __align__(8)   int    adj_s[K_][32];
    __shared__ __align__(128) float  outbuf[32 * MPAD];   // padded rows (~16.5 KB)
    __shared__ float s_cos[P_], s_sin[P_], s_q[D_], s_nh;

    const int tid    = threadIdx.x;
    const int base_m = blockIdx.x * 32;            // block covers 32 m
    const int nb     = base_m & (N_ - 1);

    // ---- stage A (pre-scaled by C_d): one (d,c,p) entry per thread ----
    {
        int p = tid & 3, c = (tid >> 2) & 7, d = tid >> 5;
        int j = c & 3, ch = c >> 2;
        float sg   = fmaxf(sigma[0], 1e-10f);
        float is2  = 1.0f / (sg * sg);
        float nhl  = -0.5f * is2;
        float norm = rsqrtf(6.283185307179586f * sg * sg);
        float td   = dists[d];
        float Cd   = expf(nhl * td * td) * norm;
        int g = p * (D_ * CI_ * CO_) + d * (CI_ * CO_) + c * CO_;
        ulonglong2 h0, h1;
        h0.x = pk2(A[g + 0] * Cd, A[g + 1] * Cd);
        h0.y = pk2(A[g + 2] * Cd, A[g + 3] * Cd);
        h1.x = pk2(A[g + 4] * Cd, A[g + 5] * Cd);
        h1.y = pk2(A[g + 6] * Cd, A[g + 7] * Cd);
        A16[a16_idx(d, j, 0, p, ch)] = h0;
        A16[a16_idx(d, j, 1, p, ch)] = h1;
    }
    // ---- stage dx/dy/adj transposed (known-good R4 path) ----
    if (tid < 72) {
        float4 xv = __ldg((const float4*)(dx + (size_t)base_m * K_) + tid);
        float4 yv = __ldg((const float4*)(dy + (size_t)base_m * K_) + tid);
        int4   av = __ldg((const int4*)  (adj + (size_t)nb * K_) + tid);
        int e = tid * 4;
        int ml, k;
        ml = (e+0)/9; k = (e+0)%9; dxy_s[k][ml].x = xv.x; dxy_s[k][ml].y = yv.x; adj_s[k][ml] = av.x;
        ml = (e+1)/9; k = (e+1)%9; dxy_s[k][ml].x = xv.y; dxy_s[k][ml].y = yv.y; adj_s[k][ml] = av.y;
        ml = (e+2)/9; k = (e+2)%9; dxy_s[k][ml].x = xv.z; dxy_s[k][ml].y = yv.z; adj_s[k][ml] = av.z;
        ml = (e+3)/9; k = (e+3)%9; dxy_s[k][ml].x = xv.w; dxy_s[k][ml].y = yv.w; adj_s[k][ml] = av.w;
    }
    if (tid == 0) {
        float sg  = fmaxf(sigma[0], 1e-10f);
        float is2 = 1.0f / (sg * sg);
        s_nh = -0.5f * is2;
        #pragma unroll
        for (int p = 0; p < P_; p++) { s_cos[p] = cosf(phis[p]); s_sin[p] = sinf(phis[p]); }
        #pragma unroll
        for (int d = 0; d < D_; d++) s_q[d] = dists[d] * is2;
    }
    __syncthreads();

    const int wid  = tid >> 5;
    const int lane = tid & 31;
    const int m4   = lane >> 3;
    const int p    = (lane >> 1) & 3;
    const int ch   = lane & 1;

    const int mlA  = wid * 8 + m4 * 2;        // block-local m of this thread's pair
    const int b    = base_m >> 17;            // uniform per block (N_ = 2^17)

    const float cosp = s_cos[p], sinp = s_sin[p], nh = s_nh;
    const float q0 = s_q[0], q1 = s_q[1], q2 = s_q[2], q3 = s_q[3];

    const float* xb = x + (size_t)b * N_ * CI_ + ch * 4;

    u64 tA[D_][2], tB[D_][2];
    #pragma unroll
    for (int d = 0; d < D_; d++) {
        tA[d][0] = 0ull; tA[d][1] = 0ull;
        tB[d][0] = 0ull; tB[d][1] = 0ull;
    }

    #pragma unroll 3
    for (int k = 0; k < K_; k++) {
        float4 dd = *(const float4*)&dxy_s[k][mlA];      // dxA,dyA,dxB,dyB
        int2   aa = *(const int2*)&adj_s[k][mlA];
        float4 xa  = __ldg((const float4*)(xb + (size_t)aa.x * CI_));
        float4 xvb = __ldg((const float4*)(xb + (size_t)aa.y * CI_));

        float ra = nh * fmaf(dd.y, dd.y, dd.x * dd.x);
        float ca = fmaf(dd.y, sinp, dd.x * cosp);
        float rb = nh * fmaf(dd.w, dd.w, dd.z * dd.z);
        float cb = fmaf(dd.w, sinp, dd.z * cosp);

        float eA0 = __expf(fmaf(ca, q0, ra));
        float eA1 = __expf(fmaf(ca, q1, ra));
        float eA2 = __expf(fmaf(ca, q2, ra));
        float eA3 = __expf(fmaf(ca, q3, ra));
        float eB0 = __expf(fmaf(cb, q0, rb));
        float eB1 = __expf(fmaf(cb, q1, rb));
        float eB2 = __expf(fmaf(cb, q2, rb));
        float eB3 = __expf(fmaf(cb, q3, rb));

        u64 xa0 = pk2(xa.x, xa.y),   xa1 = pk2(xa.z, xa.w);
        u64 xb0 = pk2(xvb.x, xvb.y), xb1 = pk2(xvb.z, xvb.w);

        u64 w;
        w = pk2(eA0, eA0); tA[0][0] = fma2(w, xa0, tA[0][0]); tA[0][1] = fma2(w, xa1, tA[0][1]);
        w = pk2(eA1, eA1); tA[1][0] = fma2(w, xa0, tA[1][0]); tA[1][1] = fma2(w, xa1, tA[1][1]);
        w = pk2(eA2, eA2); tA[2][0] = fma2(w, xa0, tA[2][0]); tA[2][1] = fma2(w, xa1, tA[2][1]);
        w = pk2(eA3, eA3); tA[3][0] = fma2(w, xa0, tA[3][0]); tA[3][1] = fma2(w, xa1, tA[3][1]);
        w = pk2(eB0, eB0); tB[0][0] = fma2(w, xb0, tB[0][0]); tB[0][1] = fma2(w, xb1, tB[0][1]);
        w = pk2(eB1, eB1); tB[1][0] = fma2(w, xb0, tB[1][0]); tB[1][1] = fma2(w, xb1, tB[1][1]);
        w = pk2(eB2, eB2); tB[2][0] = fma2(w, xb0, tB[2][0]); tB[2][1] = fma2(w, xb1, tB[2][1]);
        w = pk2(eB3, eB3); tB[3][0] = fma2(w, xb0, tB[3][0]); tB[3][1] = fma2(w, xb1, tB[3][1]);
    }

    // ---- contraction (R12 structure: exchange-acc AFTER the FMAs) ----
    float* oA = outbuf + mlA * MPAD + p * (D_ * CO_);
    float* oB = oA + MPAD;
    const int sel = p & 1;     // p-parity h-rotation; MPAD injects m4 into banks

    #pragma unroll
    for (int dk = 0; dk < 2; dk++) {
        const int d0 = dk, d1 = dk + 2;

        float tA0[4], tA1[4], tB0[4], tB1[4];
        upk2(tA0[0], tA0[1], tA[d0][0]);
        upk2(tA0[2], tA0[3], tA[d0][1]);
        upk2(tA1[0], tA1[1], tA[d1][0]);
        upk2(tA1[2], tA1[3], tA[d1][1]);
        upk2(tB0[0], tB0[1], tB[d0][0]);
        upk2(tB0[2], tB0[3], tB[d0][1]);
        upk2(tB1[0], tB1[1], tB[d1][0]);
        upk2(tB1[2], tB1[3], tB[d1][1]);

        u64 aA0[4] = {0,0,0,0}, aA1[4] = {0,0,0,0};
        u64 aB0[4] = {0,0,0,0}, aB1[4] = {0,0,0,0};
        #pragma unroll
        for (int j = 0; j < 4; j++) {
            ulonglong2 e0 = A16[a16_idx(d0, j, 0, p, ch)];
            ulonglong2 e1 = A16[a16_idx(d0, j, 1, p, ch)];
            u64 t_;
            t_ = pk2(tA0[j], tA0[j]);
            aA0[0] = fma2(t_, e0.x, aA0[0]); aA0[1] = fma2(t_, e0.y, aA0[1]);
            aA0[2] = fma2(t_, e1.x, aA0[2]); aA0[3] = fma2(t_, e1.y, aA0[3]);
            t_ = pk2(tB0[j], tB0[j]);
            aB0[0] = fma2(t_, e0.x, aB0[0]); aB0[1] = fma2(t_, e0.y, aB0[1]);
            aB0[2] = fma2(t_, e1.x, aB0[2]); aB0[3] = fma2(t_, e1.y, aB0[3]);

            ulonglong2 f0 = A16[a16_idx(d1, j, 0, p, ch)];
            ulonglong2 f1 = A16[a16_idx(d1, j, 1, p, ch)];
            t_ = pk2(tA1[j], tA1[j]);
            aA1[0] = fma2(t_, f0.x, aA1[0]); aA1[1] = fma2(t_, f0.y, aA1[1]);
            aA1[2] = fma2(t_, f1.x, aA1[2]); aA1[3] = fma2(t_, f1.y, aA1[3]);
            t_ = pk2(tB1[j], tB1[j]);
            aB1[0] = fma2(t_, f0.x, aB1[0]); aB1[1] = fma2(t_, f0.y, aB1[1]);
            aB1[2] = fma2(t_, f1.x, aB1[2]); aB1[3] = fma2(t_, f1.y, aB1[3]);
        }

        // exchange with partner lane (other c-half). Kept d = dk + 2*ch.
        u64 finA[4], finB[4];
        #pragma unroll
        for (int o2 = 0; o2 < 4; o2++) {
            u64 sA = ch ? aA0[o2] : aA1[o2];
            u64 rA = __shfl_xor_sync(0xffffffffu, sA, 1);
            u64 kA = ch ? aA1[o2] : aA0[o2];
            finA[o2] = add2(kA, rA);
            u64 sB = ch ? aB0[o2] : aB1[o2];
            u64 rB = __shfl_xor_sync(0xffffffffu, sB, 1);
            u64 kB = ch ? aB1[o2] : aB0[o2];
            finB[o2] = add2(kB, rB);
        }

        // stage: p-rotated chunk order + MPAD m4-injection -> ~4-way STS
        const int dkeepf = (2 * ch + dk) * CO_;   // float offset of kept d row
        ulonglong2 vlo, vhi;
        vlo.x = finA[0]; vlo.y = finA[1];
        vhi.x = finA[2]; vhi.y = finA[3];
        *(ulonglong2*)(oA + dkeepf + sel * 4)        = sel ? vhi : vlo;
        *(ulonglong2*)(oA + dkeepf + (sel ^ 1) * 4)  = sel ? vlo : vhi;
        vlo.x = finB[0]; vlo.y = finB[1];
        vhi.x = finB[2]; vhi.y = finB[3];
        *(ulonglong2*)(oB + dkeepf + sel * 4)        = sel ? vhi : vlo;
        *(ulonglong2*)(oB + dkeepf + (sel ^ 1) * 4)  = sel ? vlo : vhi;
    }
    __syncthreads();

    // ---- TMA epilogue: 32 x 512B bulk stores, all issued by tid 0 ----
    if (tid == 0) {
        asm volatile("fence.proxy.async.shared::cta;" ::: "memory");
        uint32_t sbase = (uint32_t)__cvta_generic_to_shared(outbuf);
        float* gdst = out + (size_t)base_m * MOUT;
        #pragma unroll
        for (int r = 0; r < 32; r++) {
            asm volatile(
                "cp.async.bulk.global.shared::cta.bulk_group [%0], [%1], %2;"
                :: "l"(gdst + r * MOUT), "r"(sbase + r * (MPAD * 4)),
                   "r"(MOUT * 4) : "memory");
        }
        asm volatile("cp.async.bulk.commit_group;" ::: "memory");
        asm volatile("cp.async.bulk.wait_group.read 0;" ::: "memory");
    }
}

extern "C" void kernel_launch(void* const* d_in, const int* in_sizes, int n_in,
                              void* d_out, int out_size)
{
    const float* x     = (const float*)d_in[0];
    const float* dx    = (const float*)d_in[1];
    const float* dy    = (const float*)d_in[2];
    const int*   adj   = (const int*)d_in[3];
    const float* phis  = (const float*)d_in[4];
    const float* dists = (const float*)d_in[5];
    const float* sigma = (const float*)d_in[6];
    const float* A     = (const float*)d_in[7];
    float* out = (float*)d_out;

    dim3 grid(NTOT / 32);   // 8192 blocks, 128 threads, each thread 2 m
    pol_kernel<<<grid, 128>>>(x, dx, dy, adj, phis, dists, sigma, A, out);
    (void)in_sizes; (void)n_in; (void)out_size;
}

// round 16
// speedup vs baseline: 1.0672x; 1.0572x over previous
#include <cuda_runtime.h>
#include <cuda.h>
#include <cstdint>

#define B_   2
#define N_   131072
#define K_   9
#define P_   4
#define D_   4
#define CI_  8
#define CO_  8
#define NTOT (B_ * N_)   // 262144
#define MOUT (P_ * D_ * CO_)   // 128 floats per m

typedef unsigned long long u64;

// ---- packed f32x2 helpers ----
__device__ __forceinline__ u64 pk2(float lo, float hi) {
    u64 r; asm("mov.b64 %0, {%1, %2};" : "=l"(r) : "f"(lo), "f"(hi)); return r;
}
__device__ __forceinline__ void upk2(float &lo, float &hi, u64 v) {
    asm("mov.b64 {%0, %1}, %2;" : "=f"(lo), "=f"(hi) : "l"(v));
}
__device__ __forceinline__ u64 fma2(u64 a, u64 b, u64 c) {
    u64 d; asm("fma.rn.f32x2 %0, %1, %2, %3;" : "=l"(d) : "l"(a), "l"(b), "l"(c)); return d;
}
__device__ __forceinline__ u64 add2(u64 a, u64 b) {
    u64 d; asm("add.rn.f32x2 %0, %1, %2;" : "=l"(d) : "l"(a), "l"(b)); return d;
}

// A (pre-scaled by C_d) in shared as 16B chunks: A16[d][j][h][p][ch]; for
// fixed (d,j,h) the 8 (p,ch) lanes hit 8 consecutive 16B chunks = one 128B
// span -> conflict-free broadcast LDS.128.   (c = ch*4 + j)
__device__ __forceinline__ int a16_idx(int d, int j, int h, int p, int ch) {
    return ((((d * 4 + j) * 2 + h) * P_ + p) * 2 + ch);
}

__global__ __launch_bounds__(128, 5)
void pol_kernel(const float* __restrict__ x,
                const float* __restrict__ dx,
                const float* __restrict__ dy,
                const int*   __restrict__ adj,
                const float* __restrict__ phis,
                const float* __restrict__ dists,
                const float* __restrict__ sigma,
                const float* __restrict__ A,
                float* __restrict__ out,
                const __grid_constant__ CUtensorMap tmap,
                const int use_tma)
{
    __shared__ __align__(16)   ulonglong2 A16[256];        // 4 KB
    __shared__ __align__(16)   float2 dxy_s[K_][32];       // [k][block-local m]
    __shared__ __align__(8)    int    adj_s[K_][32];
    __shared__ __align__(1024) float  outbuf[32 * MOUT];   // 16 KB (SW128 layout if use_tma)
    __shared__ float s_cos[P_], s_sin[P_], s_q[D_], s_nh;

    const int tid    = threadIdx.x;
    const int base_m = blockIdx.x * 32;            // block covers 32 m
    const int nb     = base_m & (N_ - 1);

    // ---- stage A (pre-scaled by C_d): one (d,c,p) entry per thread ----
    {
        int p = tid & 3, c = (tid >> 2) & 7, d = tid >> 5;
        int j = c & 3, ch = c >> 2;
        float sg   = fmaxf(sigma[0], 1e-10f);
        float is2  = 1.0f / (sg * sg);
        float nhl  = -0.5f * is2;
        float norm = rsqrtf(6.283185307179586f * sg * sg);
        float td   = dists[d];
        float Cd   = expf(nhl * td * td) * norm;
        int g = p * (D_ * CI_ * CO_) + d * (CI_ * CO_) + c * CO_;
        ulonglong2 h0, h1;
        h0.x = pk2(A[g + 0] * Cd, A[g + 1] * Cd);
        h0.y = pk2(A[g + 2] * Cd, A[g + 3] * Cd);
        h1.x = pk2(A[g + 4] * Cd, A[g + 5] * Cd);
        h1.y = pk2(A[g + 6] * Cd, A[g + 7] * Cd);
        A16[a16_idx(d, j, 0, p, ch)] = h0;
        A16[a16_idx(d, j, 1, p, ch)] = h1;
    }
    // ---- stage dx/dy/adj transposed (known-good R4 path) ----
    if (tid < 72) {
        float4 xv = __ldg((const float4*)(dx + (size_t)base_m * K_) + tid);
        float4 yv = __ldg((const float4*)(dy + (size_t)base_m * K_) + tid);
        int4   av = __ldg((const int4*)  (adj + (size_t)nb * K_) + tid);
        int e = tid * 4;
        int ml, k;
        ml = (e+0)/9; k = (e+0)%9; dxy_s[k][ml].x = xv.x; dxy_s[k][ml].y = yv.x; adj_s[k][ml] = av.x;
        ml = (e+1)/9; k = (e+1)%9; dxy_s[k][ml].x = xv.y; dxy_s[k][ml].y = yv.y; adj_s[k][ml] = av.y;
        ml = (e+2)/9; k = (e+2)%9; dxy_s[k][ml].x = xv.z; dxy_s[k][ml].y = yv.z; adj_s[k][ml] = av.z;
        ml = (e+3)/9; k = (e+3)%9; dxy_s[k][ml].x = xv.w; dxy_s[k][ml].y = yv.w; adj_s[k][ml] = av.w;
    }
    if (tid == 0) {
        float sg  = fmaxf(sigma[0], 1e-10f);
        float is2 = 1.0f / (sg * sg);
        s_nh = -0.5f * is2;
        #pragma unroll
        for (int p = 0; p < P_; p++) { s_cos[p] = cosf(phis[p]); s_sin[p] = sinf(phis[p]); }
        #pragma unroll
        for (int d = 0; d < D_; d++) s_q[d] = dists[d] * is2;
    }
    __syncthreads();

    const int wid  = tid >> 5;
    const int lane = tid & 31;
    const int m4   = lane >> 3;
    const int p    = (lane >> 1) & 3;
    const int ch   = lane & 1;

    const int mlA  = wid * 8 + m4 * 2;        // block-local m of this thread's pair
    const int b    = base_m >> 17;            // uniform per block (N_ = 2^17)

    const float cosp = s_cos[p], sinp = s_sin[p], nh = s_nh;
    const float q0 = s_q[0], q1 = s_q[1], q2 = s_q[2], q3 = s_q[3];

    const float* xb = x + (size_t)b * N_ * CI_ + ch * 4;

    u64 tA[D_][2], tB[D_][2];
    #pragma unroll
    for (int d = 0; d < D_; d++) {
        tA[d][0] = 0ull; tA[d][1] = 0ull;
        tB[d][0] = 0ull; tB[d][1] = 0ull;
    }

    #pragma unroll 3
    for (int k = 0; k < K_; k++) {
        float4 dd = *(const float4*)&dxy_s[k][mlA];      // dxA,dyA,dxB,dyB
        int2   aa = *(const int2*)&adj_s[k][mlA];
        float4 xa  = __ldg((const float4*)(xb + (size_t)aa.x * CI_));
        float4 xvb = __ldg((const float4*)(xb + (size_t)aa.y * CI_));

        float ra = nh * fmaf(dd.y, dd.y, dd.x * dd.x);
        float ca = fmaf(dd.y, sinp, dd.x * cosp);
        float rb = nh * fmaf(dd.w, dd.w, dd.z * dd.z);
        float cb = fmaf(dd.w, sinp, dd.z * cosp);

        float eA0 = __expf(fmaf(ca, q0, ra));
        float eA1 = __expf(fmaf(ca, q1, ra));
        float eA2 = __expf(fmaf(ca, q2, ra));
        float eA3 = __expf(fmaf(ca, q3, ra));
        float eB0 = __expf(fmaf(cb, q0, rb));
        float eB1 = __expf(fmaf(cb, q1, rb));
        float eB2 = __expf(fmaf(cb, q2, rb));
        float eB3 = __expf(fmaf(cb, q3, rb));

        u64 xa0 = pk2(xa.x, xa.y),   xa1 = pk2(xa.z, xa.w);
        u64 xb0 = pk2(xvb.x, xvb.y), xb1 = pk2(xvb.z, xvb.w);

        u64 w;
        w = pk2(eA0, eA0); tA[0][0] = fma2(w, xa0, tA[0][0]); tA[0][1] = fma2(w, xa1, tA[0][1]);
        w = pk2(eA1, eA1); tA[1][0] = fma2(w, xa0, tA[1][0]); tA[1][1] = fma2(w, xa1, tA[1][1]);
        w = pk2(eA2, eA2); tA[2][0] = fma2(w, xa0, tA[2][0]); tA[2][1] = fma2(w, xa1, tA[2][1]);
        w = pk2(eA3, eA3); tA[3][0] = fma2(w, xa0, tA[3][0]); tA[3][1] = fma2(w, xa1, tA[3][1]);
        w = pk2(eB0, eB0); tB[0][0] = fma2(w, xb0, tB[0][0]); tB[0][1] = fma2(w, xb1, tB[0][1]);
        w = pk2(eB1, eB1); tB[1][0] = fma2(w, xb0, tB[1][0]); tB[1][1] = fma2(w, xb1, tB[1][1]);
        w = pk2(eB2, eB2); tB[2][0] = fma2(w, xb0, tB[2][0]); tB[2][1] = fma2(w, xb1, tB[2][1]);
        w = pk2(eB3, eB3); tB[3][0] = fma2(w, xb0, tB[3][0]); tB[3][1] = fma2(w, xb1, tB[3][1]);
    }

    // ---- contraction (R12 structure: exchange-acc AFTER the FMAs) ----
    // SW128-swizzled store bases (per-thread constants, zero value SELs).
    // logical byte offset = m*512 + p*128 + dkeep*32 + h*16; smem row = m*4+p,
    // TMA SW128 xor = ((row&7)<<4) = ((4*(m&1)+p)<<4).  (m&1: mA even, mB odd)
    const int xorA = use_tma ? (p << 4) : 0;
    const int xorB = use_tma ? ((4 | p) << 4) : 0;
    char* cbA = (char*)outbuf + mlA * 512 + p * 128;
    char* cbB = cbA + 512;

    #pragma unroll
    for (int dk = 0; dk < 2; dk++) {
        const int d0 = dk, d1 = dk + 2;

        float tA0[4], tA1[4], tB0[4], tB1[4];
        upk2(tA0[0], tA0[1], tA[d0][0]);
        upk2(tA0[2], tA0[3], tA[d0][1]);
        upk2(tA1[0], tA1[1], tA[d1][0]);
        upk2(tA1[2], tA1[3], tA[d1][1]);
        upk2(tB0[0], tB0[1], tB[d0][0]);
        upk2(tB0[2], tB0[3], tB[d0][1]);
        upk2(tB1[0], tB1[1], tB[d1][0]);
        upk2(tB1[2], tB1[3], tB[d1][1]);

        u64 aA0[4] = {0,0,0,0}, aA1[4] = {0,0,0,0};
        u64 aB0[4] = {0,0,0,0}, aB1[4] = {0,0,0,0};
        #pragma unroll
        for (int j = 0; j < 4; j++) {
            ulonglong2 e0 = A16[a16_idx(d0, j, 0, p, ch)];
            ulonglong2 e1 = A16[a16_idx(d0, j, 1, p, ch)];
            u64 t_;
            t_ = pk2(tA0[j], tA0[j]);
            aA0[0] = fma2(t_, e0.x, aA0[0]); aA0[1] = fma2(t_, e0.y, aA0[1]);
            aA0[2] = fma2(t_, e1.x, aA0[2]); aA0[3] = fma2(t_, e1.y, aA0[3]);
            t_ = pk2(tB0[j], tB0[j]);
            aB0[0] = fma2(t_, e0.x, aB0[0]); aB0[1] = fma2(t_, e0.y, aB0[1]);
            aB0[2] = fma2(t_, e1.x, aB0[2]); aB0[3] = fma2(t_, e1.y, aB0[3]);

            ulonglong2 f0 = A16[a16_idx(d1, j, 0, p, ch)];
            ulonglong2 f1 = A16[a16_idx(d1, j, 1, p, ch)];
            t_ = pk2(tA1[j], tA1[j]);
            aA1[0] = fma2(t_, f0.x, aA1[0]); aA1[1] = fma2(t_, f0.y, aA1[1]);
            aA1[2] = fma2(t_, f1.x, aA1[2]); aA1[3] = fma2(t_, f1.y, aA1[3]);
            t_ = pk2(tB1[j], tB1[j]);
            aB1[0] = fma2(t_, f0.x, aB1[0]); aB1[1] = fma2(t_, f0.y, aB1[1]);
            aB1[2] = fma2(t_, f1.x, aB1[2]); aB1[3] = fma2(t_, f1.y, aB1[3]);
        }

        // exchange with partner lane (other c-half). Kept d = dk + 2*ch.
        u64 finA[4], finB[4];
        #pragma unroll
        for (int o2 = 0; o2 < 4; o2++) {
            u64 sA = ch ? aA0[o2] : aA1[o2];
            u64 rA = __shfl_xor_sync(0xffffffffu, sA, 1);
            u64 kA = ch ? aA1[o2] : aA0[o2];
            finA[o2] = add2(kA, rA);
            u64 sB = ch ? aB0[o2] : aB1[o2];
            u64 rB = __shfl_xor_sync(0xffffffffu, sB, 1);
            u64 kB = ch ? aB1[o2] : aB0[o2];
            finB[o2] = add2(kB, rB);
        }

        // SW128-swizzled STS: granule = 4ch^4(m&1) + ((2dk+h)^p) -> 4-way (floor)
        const int offd = (2 * ch + dk) * 32;   // kept-d byte offset within quarter
        ulonglong2 vlo, vhi;
        vlo.x = finA[0]; vlo.y = finA[1];
        vhi.x = finA[2]; vhi.y = finA[3];
        *(ulonglong2*)(cbA + (offd ^ xorA))        = vlo;
        *(ulonglong2*)(cbA + ((offd + 16) ^ xorA)) = vhi;
        vlo.x = finB[0]; vlo.y = finB[1];
        vhi.x = finB[2]; vhi.y = finB[3];
        *(ulonglong2*)(cbB + (offd ^ xorB))        = vlo;
        *(ulonglong2*)(cbB + ((offd + 16) ^ xorB)) = vhi;
    }
    __syncthreads();

    // ---- single TMA store: tensor (SW128 de-swizzle) or linear fallback ----
    if (tid == 0) {
        asm volatile("fence.proxy.async.shared::cta;" ::: "memory");
        uint32_t saddr = (uint32_t)__cvta_generic_to_shared(outbuf);
        if (use_tma) {
            asm volatile(
                "cp.async.bulk.tensor.2d.global.shared::cta.tile.bulk_group "
                "[%0, {%1, %2}], [%3];"
                :: "l"(&tmap), "r"(0), "r"(base_m * 4), "r"(saddr) : "memory");
        } else {
            float* gdst = out + (size_t)base_m * MOUT;
            asm volatile(
                "cp.async.bulk.global.shared::cta.bulk_group [%0], [%1], %2;"
                :: "l"(gdst), "r"(saddr), "r"(32 * MOUT * 4) : "memory");
        }
        asm volatile("cp.async.bulk.commit_group;" ::: "memory");
        asm volatile("cp.async.bulk.wait_group.read 0;" ::: "memory");
    }
}

extern "C" void kernel_launch(void* const* d_in, const int* in_sizes, int n_in,
                              void* d_out, int out_size)
{
    const float* x     = (const float*)d_in[0];
    const float* dx    = (const float*)d_in[1];
    const float* dy    = (const float*)d_in[2];
    const int*   adj   = (const int*)d_in[3];
    const float* phis  = (const float*)d_in[4];
    const float* dists = (const float*)d_in[5];
    const float* sigma = (const float*)d_in[6];
    const float* A     = (const float*)d_in[7];
    float* out = (float*)d_out;

    // Encode the SW128 tensormap for `out` viewed as [32 floats x NTOT*4 rows].
    // Driver API fetched via cudart (no -lcuda link dependency). Deterministic:
    // re-done every call, no caching, no allocation.
    alignas(64) CUtensorMap tmap;
    int use_tma = 0;
    {
        typedef CUresult (*EncT)(CUtensorMap*, CUtensorMapDataType, cuuint32_t,
                                 void*, const cuuint64_t*, const cuuint64_t*,
                                 const cuuint32_t*, const cuuint32_t*,
                                 CUtensorMapInterleave, CUtensorMapSwizzle,
                                 CUtensorMapL2promotion, CUtensorMapFloatOOBfill);
        void* fn = nullptr;
        cudaDriverEntryPointQueryResult qres = cudaDriverEntryPointSymbolNotFound;
        if (cudaGetDriverEntryPoint("cuTensorMapEncodeTiled", &fn,
                                    cudaEnableDefault, &qres) == cudaSuccess &&
            qres == cudaDriverEntryPointSuccess && fn != nullptr) {
            cuuint64_t dims[2]    = {32, (cuuint64_t)NTOT * 4};
            cuuint64_t strides[1] = {128};
            cuuint32_t box[2]     = {32, 128};
            cuuint32_t es[2]      = {1, 1};
            EncT enc = (EncT)fn;
            if (enc(&tmap, CU_TENSOR_MAP_DATA_TYPE_FLOAT32, 2, d_out,
                    dims, strides, box, es,
                    CU_TENSOR_MAP_INTERLEAVE_NONE, CU_TENSOR_MAP_SWIZZLE_128B,
                    CU_TENSOR_MAP_L2_PROMOTION_L2_128B,
                    CU_TENSOR_MAP_FLOAT_OOB_FILL_NONE) == CUDA_SUCCESS) {
                use_tma = 1;
            }
        }
    }

    dim3 grid(NTOT / 32);   // 8192 blocks, 128 threads, each thread 2 m
    pol_kernel<<<grid, 128>>>(x, dx, dy, adj, phis, dists, sigma, A, out,
                              tmap, use_tma);
    (void)in_sizes; (void)n_in; (void)out_size;
}

// round 17
// speedup vs baseline: 1.1235x; 1.0528x over previous
#include <cuda_runtime.h>
#include <cuda.h>
#include <cstdint>

#define B_   2
#define N_   131072
#define K_   9
#define P_   4
#define D_   4
#define CI_  8
#define CO_  8
#define NTOT (B_ * N_)   // 262144
#define MOUT (P_ * D_ * CO_)   // 128 floats per m

typedef unsigned long long u64;

// ---- packed f32x2 helpers ----
__device__ __forceinline__ u64 pk2(float lo, float hi) {
    u64 r; asm("mov.b64 %0, {%1, %2};" : "=l"(r) : "f"(lo), "f"(hi)); return r;
}
__device__ __forceinline__ void upk2(float &lo, float &hi, u64 v) {
    asm("mov.b64 {%0, %1}, %2;" : "=f"(lo), "=f"(hi) : "l"(v));
}
__device__ __forceinline__ u64 fma2(u64 a, u64 b, u64 c) {
    u64 d; asm("fma.rn.f32x2 %0, %1, %2, %3;" : "=l"(d) : "l"(a), "l"(b), "l"(c)); return d;
}
__device__ __forceinline__ u64 add2(u64 a, u64 b) {
    u64 d; asm("add.rn.f32x2 %0, %1, %2;" : "=l"(d) : "l"(a), "l"(b)); return d;
}

// A (pre-scaled by C_d) in shared as 16B chunks: A16[d][j][h][p][ch]; for
// fixed (d,j,h) the 8 (p,ch) lanes hit 8 consecutive 16B chunks = one 128B
// span -> conflict-free broadcast LDS.128.   (c = ch*4 + j)
__device__ __forceinline__ int a16_idx(int d, int j, int h, int p, int ch) {
    return ((((d * 4 + j) * 2 + h) * P_ + p) * 2 + ch);
}

__global__ __launch_bounds__(128, 5)
void pol_kernel(const float* __restrict__ x,
                const float* __restrict__ dx,
                const float* __restrict__ dy,
                const int*   __restrict__ adj,
                const float* __restrict__ phis,
                const float* __restrict__ dists,
                const float* __restrict__ sigma,
                const float* __restrict__ A,
                float* __restrict__ out,
                const __grid_constant__ CUtensorMap tmap,
                const int use_tma)
{
    __shared__ __align__(16)   ulonglong2 A16[256];        // 4 KB
    __shared__ __align__(16)   float2 dxy_s[K_][32];       // [k][block-local m]
    __shared__ __align__(8)    int    adj_s[K_][32];
    __shared__ __align__(1024) float  outbuf[32 * MOUT];   // 16 KB (SW128 layout if use_tma)
    __shared__ float s_cos[P_], s_sin[P_], s_q[D_], s_nh;

    const int tid    = threadIdx.x;
    const int base_m = blockIdx.x * 32;            // block covers 32 m
    const int nb     = base_m & (N_ - 1);

    // ---- stage A (pre-scaled by C_d): one (d,c,p) entry per thread ----
    {
        int p = tid & 3, c = (tid >> 2) & 7, d = tid >> 5;
        int j = c & 3, ch = c >> 2;
        float sg   = fmaxf(sigma[0], 1e-10f);
        float is2  = 1.0f / (sg * sg);
        float nhl  = -0.5f * is2;
        float norm = rsqrtf(6.283185307179586f * sg * sg);
        float td   = dists[d];
        float Cd   = expf(nhl * td * td) * norm;
        int g = p * (D_ * CI_ * CO_) + d * (CI_ * CO_) + c * CO_;
        ulonglong2 h0, h1;
        h0.x = pk2(A[g + 0] * Cd, A[g + 1] * Cd);
        h0.y = pk2(A[g + 2] * Cd, A[g + 3] * Cd);
        h1.x = pk2(A[g + 4] * Cd, A[g + 5] * Cd);
        h1.y = pk2(A[g + 6] * Cd, A[g + 7] * Cd);
        A16[a16_idx(d, j, 0, p, ch)] = h0;
        A16[a16_idx(d, j, 1, p, ch)] = h1;
    }
    // ---- stage dx/dy/adj transposed (known-good R4 path) ----
    if (tid < 72) {
        float4 xv = __ldg((const float4*)(dx + (size_t)base_m * K_) + tid);
        float4 yv = __ldg((const float4*)(dy + (size_t)base_m * K_) + tid);
        int4   av = __ldg((const int4*)  (adj + (size_t)nb * K_) + tid);
        int e = tid * 4;
        int ml, k;
        ml = (e+0)/9; k = (e+0)%9; dxy_s[k][ml].x = xv.x; dxy_s[k][ml].y = yv.x; adj_s[k][ml] = av.x;
        ml = (e+1)/9; k = (e+1)%9; dxy_s[k][ml].x = xv.y; dxy_s[k][ml].y = yv.y; adj_s[k][ml] = av.y;
        ml = (e+2)/9; k = (e+2)%9; dxy_s[k][ml].x = xv.z; dxy_s[k][ml].y = yv.z; adj_s[k][ml] = av.z;
        ml = (e+3)/9; k = (e+3)%9; dxy_s[k][ml].x = xv.w; dxy_s[k][ml].y = yv.w; adj_s[k][ml] = av.w;
    }
    if (tid == 0) {
        float sg  = fmaxf(sigma[0], 1e-10f);
        float is2 = 1.0f / (sg * sg);
        s_nh = -0.5f * is2;
        #pragma unroll
        for (int p = 0; p < P_; p++) { s_cos[p] = cosf(phis[p]); s_sin[p] = sinf(phis[p]); }
        #pragma unroll
        for (int d = 0; d < D_; d++) s_q[d] = dists[d] * is2;
    }
    __syncthreads();

    const int wid  = tid >> 5;
    const int lane = tid & 31;
    const int m4   = lane >> 3;
    const int p    = (lane >> 1) & 3;
    const int ch   = lane & 1;

    const int mlA  = wid * 8 + m4 * 2;        // block-local m of this thread's pair
    const int b    = base_m >> 17;            // uniform per block (N_ = 2^17)

    const float cosp = s_cos[p], sinp = s_sin[p], nh = s_nh;
    const float q0 = s_q[0], q1 = s_q[1], q2 = s_q[2], q3 = s_q[3];

    const float* xb = x + (size_t)b * N_ * CI_ + ch * 4;

    u64 tA[D_][2], tB[D_][2];
    #pragma unroll
    for (int d = 0; d < D_; d++) {
        tA[d][0] = 0ull; tA[d][1] = 0ull;
        tB[d][0] = 0ull; tB[d][1] = 0ull;
    }

    #pragma unroll
    for (int k = 0; k < K_; k++) {
        float4 dd = *(const float4*)&dxy_s[k][mlA];      // dxA,dyA,dxB,dyB
        int2   aa = *(const int2*)&adj_s[k][mlA];
        float4 xa  = __ldg((const float4*)(xb + (size_t)aa.x * CI_));
        float4 xvb = __ldg((const float4*)(xb + (size_t)aa.y * CI_));

        float ra = nh * fmaf(dd.y, dd.y, dd.x * dd.x);
        float ca = fmaf(dd.y, sinp, dd.x * cosp);
        float rb = nh * fmaf(dd.w, dd.w, dd.z * dd.z);
        float cb = fmaf(dd.w, sinp, dd.z * cosp);

        float eA0 = __expf(fmaf(ca, q0, ra));
        float eA1 = __expf(fmaf(ca, q1, ra));
        float eA2 = __expf(fmaf(ca, q2, ra));
        float eA3 = __expf(fmaf(ca, q3, ra));
        float eB0 = __expf(fmaf(cb, q0, rb));
        float eB1 = __expf(fmaf(cb, q1, rb));
        float eB2 = __expf(fmaf(cb, q2, rb));
        float eB3 = __expf(fmaf(cb, q3, rb));

        u64 xa0 = pk2(xa.x, xa.y),   xa1 = pk2(xa.z, xa.w);
        u64 xb0 = pk2(xvb.x, xvb.y), xb1 = pk2(xvb.z, xvb.w);

        u64 w;
        w = pk2(eA0, eA0); tA[0][0] = fma2(w, xa0, tA[0][0]); tA[0][1] = fma2(w, xa1, tA[0][1]);
        w = pk2(eA1, eA1); tA[1][0] = fma2(w, xa0, tA[1][0]); tA[1][1] = fma2(w, xa1, tA[1][1]);
        w = pk2(eA2, eA2); tA[2][0] = fma2(w, xa0, tA[2][0]); tA[2][1] = fma2(w, xa1, tA[2][1]);
        w = pk2(eA3, eA3); tA[3][0] = fma2(w, xa0, tA[3][0]); tA[3][1] = fma2(w, xa1, tA[3][1]);
        w = pk2(eB0, eB0); tB[0][0] = fma2(w, xb0, tB[0][0]); tB[0][1] = fma2(w, xb1, tB[0][1]);
        w = pk2(eB1, eB1); tB[1][0] = fma2(w, xb0, tB[1][0]); tB[1][1] = fma2(w, xb1, tB[1][1]);
        w = pk2(eB2, eB2); tB[2][0] = fma2(w, xb0, tB[2][0]); tB[2][1] = fma2(w, xb1, tB[2][1]);
        w = pk2(eB3, eB3); tB[3][0] = fma2(w, xb0, tB[3][0]); tB[3][1] = fma2(w, xb1, tB[3][1]);
    }

    // ---- contraction (R12 structure: exchange-acc AFTER the FMAs) ----
    // SW128-swizzled store bases (per-thread constants, zero value SELs).
    const int xorA = use_tma ? (p << 4) : 0;
    const int xorB = use_tma ? ((4 | p) << 4) : 0;
    char* cbA = (char*)outbuf + mlA * 512 + p * 128;
    char* cbB = cbA + 512;

    #pragma unroll
    for (int dk = 0; dk < 2; dk++) {
        const int d0 = dk, d1 = dk + 2;

        float tA0[4], tA1[4], tB0[4], tB1[4];
        upk2(tA0[0], tA0[1], tA[d0][0]);
        upk2(tA0[2], tA0[3], tA[d0][1]);
        upk2(tA1[0], tA1[1], tA[d1][0]);
        upk2(tA1[2], tA1[3], tA[d1][1]);
        upk2(tB0[0], tB0[1], tB[d0][0]);
        upk2(tB0[2], tB0[3], tB[d0][1]);
        upk2(tB1[0], tB1[1], tB[d1][0]);
        upk2(tB1[2], tB1[3], tB[d1][1]);

        u64 aA0[4] = {0,0,0,0}, aA1[4] = {0,0,0,0};
        u64 aB0[4] = {0,0,0,0}, aB1[4] = {0,0,0,0};
        #pragma unroll
        for (int j = 0; j < 4; j++) {
            ulonglong2 e0 = A16[a16_idx(d0, j, 0, p, ch)];
            ulonglong2 e1 = A16[a16_idx(d0, j, 1, p, ch)];
            u64 t_;
            t_ = pk2(tA0[j], tA0[j]);
            aA0[0] = fma2(t_, e0.x, aA0[0]); aA0[1] = fma2(t_, e0.y, aA0[1]);
            aA0[2] = fma2(t_, e1.x, aA0[2]); aA0[3] = fma2(t_, e1.y, aA0[3]);
            t_ = pk2(tB0[j], tB0[j]);
            aB0[0] = fma2(t_, e0.x, aB0[0]); aB0[1] = fma2(t_, e0.y, aB0[1]);
            aB0[2] = fma2(t_, e1.x, aB0[2]); aB0[3] = fma2(t_, e1.y, aB0[3]);

            ulonglong2 f0 = A16[a16_idx(d1, j, 0, p, ch)];
            ulonglong2 f1 = A16[a16_idx(d1, j, 1, p, ch)];
            t_ = pk2(tA1[j], tA1[j]);
            aA1[0] = fma2(t_, f0.x, aA1[0]); aA1[1] = fma2(t_, f0.y, aA1[1]);
            aA1[2] = fma2(t_, f1.x, aA1[2]); aA1[3] = fma2(t_, f1.y, aA1[3]);
            t_ = pk2(tB1[j], tB1[j]);
            aB1[0] = fma2(t_, f0.x, aB1[0]); aB1[1] = fma2(t_, f0.y, aB1[1]);
            aB1[2] = fma2(t_, f1.x, aB1[2]); aB1[3] = fma2(t_, f1.y, aB1[3]);
        }

        // exchange with partner lane (other c-half). Kept d = dk + 2*ch.
        u64 finA[4], finB[4];
        #pragma unroll
        for (int o2 = 0; o2 < 4; o2++) {
            u64 sA = ch ? aA0[o2] : aA1[o2];
            u64 rA = __shfl_xor_sync(0xffffffffu, sA, 1);
            u64 kA = ch ? aA1[o2] : aA0[o2];
            finA[o2] = add2(kA, rA);
            u64 sB = ch ? aB0[o2] : aB1[o2];
            u64 rB = __shfl_xor_sync(0xffffffffu, sB, 1);
            u64 kB = ch ? aB1[o2] : aB0[o2];
            finB[o2] = add2(kB, rB);
        }

        // SW128-swizzled STS: granule = 4ch^4(m&1) + ((2dk+h)^p) -> 4-way (floor)
        const int offd = (2 * ch + dk) * 32;   // kept-d byte offset within quarter
        ulonglong2 vlo, vhi;
        vlo.x = finA[0]; vlo.y = finA[1];
        vhi.x = finA[2]; vhi.y = finA[3];
        *(ulonglong2*)(cbA + (offd ^ xorA))        = vlo;
        *(ulonglong2*)(cbA + ((offd + 16) ^ xorA)) = vhi;
        vlo.x = finB[0]; vlo.y = finB[1];
        vhi.x = finB[2]; vhi.y = finB[3];
        *(ulonglong2*)(cbB + (offd ^ xorB))        = vlo;
        *(ulonglong2*)(cbB + ((offd + 16) ^ xorB)) = vhi;
    }
    __syncthreads();

    // ---- single TMA store: tensor (SW128 de-swizzle) or linear fallback ----
    if (tid == 0) {
        asm volatile("fence.proxy.async.shared::cta;" ::: "memory");
        uint32_t saddr = (uint32_t)__cvta_generic_to_shared(outbuf);
        if (use_tma) {
            asm volatile(
                "cp.async.bulk.tensor.2d.global.shared::cta.tile.bulk_group "
                "[%0, {%1, %2}], [%3];"
                :: "l"(&tmap), "r"(0), "r"(base_m * 4), "r"(saddr) : "memory");
        } else {
            float* gdst = out + (size_t)base_m * MOUT;
            asm volatile(
                "cp.async.bulk.global.shared::cta.bulk_group [%0], [%1], %2;"
                :: "l"(gdst), "r"(saddr), "r"(32 * MOUT * 4) : "memory");
        }
        asm volatile("cp.async.bulk.commit_group;" ::: "memory");
        asm volatile("cp.async.bulk.wait_group.read 0;" ::: "memory");
    }
}

extern "C" void kernel_launch(void* const* d_in, const int* in_sizes, int n_in,
                              void* d_out, int out_size)
{
    const float* x     = (const float*)d_in[0];
    const float* dx    = (const float*)d_in[1];
    const float* dy    = (const float*)d_in[2];
    const int*   adj   = (const int*)d_in[3];
    const float* phis  = (const float*)d_in[4];
    const float* dists = (const float*)d_in[5];
    const float* sigma = (const float*)d_in[6];
    const float* A     = (const float*)d_in[7];
    float* out = (float*)d_out;

    // Encode the SW128 tensormap for `out` viewed as [32 floats x NTOT*4 rows].
    alignas(64) CUtensorMap tmap;
    int use_tma = 0;
    {
        typedef CUresult (*EncT)(CUtensorMap*, CUtensorMapDataType, cuuint32_t,
                                 void*, const cuuint64_t*, const cuuint64_t*,
                                 const cuuint32_t*, const cuuint32_t*,
                                 CUtensorMapInterleave, CUtensorMapSwizzle,
                                 CUtensorMapL2promotion, CUtensorMapFloatOOBfill);
        void* fn = nullptr;
        cudaDriverEntryPointQueryResult qres = cudaDriverEntryPointSymbolNotFound;
        if (cudaGetDriverEntryPoint("cuTensorMapEncodeTiled", &fn,
                                    cudaEnableDefault, &qres) == cudaSuccess &&
            qres == cudaDriverEntryPointSuccess && fn != nullptr) {
            cuuint64_t dims[2]    = {32, (cuuint64_t)NTOT * 4};
            cuuint64_t strides[1] = {128};
            cuuint32_t box[2]     = {32, 128};
            cuuint32_t es[2]      = {1, 1};
            EncT enc = (EncT)fn;
            if (enc(&tmap, CU_TENSOR_MAP_DATA_TYPE_FLOAT32, 2, d_out,
                    dims, strides, box, es,
                    CU_TENSOR_MAP_INTERLEAVE_NONE, CU_TENSOR_MAP_SWIZZLE_128B,
                    CU_TENSOR_MAP_L2_PROMOTION_L2_128B,
                    CU_TENSOR_MAP_FLOAT_OOB_FILL_NONE) == CUDA_SUCCESS) {
                use_tma = 1;
            }
        }
    }

    dim3 grid(NTOT / 32);   // 8192 blocks, 128 threads, each thread 2 m
    pol_kernel<<<grid, 128>>>(x, dx, dy, adj, phis, dists, sigma, A, out,
                              tmap, use_tma);
    (void)in_sizes; (void)n_in; (void)out_size;
}